// round 15
// baseline (speedup 1.0000x reference)
#include <cuda_runtime.h>
#include <cuda_bf16.h>
#include <math.h>
#include <cstdint>

#define N_NODES 50000
#define N_EDGES 800000
#define HEADS 8
#define HID 64
#define CLAMP_V 5.0f
#define LOG2E 1.44269504088896f

// ---------------- device scratch (zero-init at module load) ----------------
__device__ float g_Q[N_NODES * HID];
__device__ float g_K[N_NODES * HID];
__device__ float g_V[N_NODES * HID];
__device__ float g_s[N_NODES * HEADS];
__device__ float g_wV[N_NODES * HID];
__device__ float g_row[N_NODES * HID];
// Pre-split weights, bf16 hi/lo, row-major [n][k]
__device__ __align__(16) unsigned short g_WhiT[192 * 64];   // [Wq|Wk|Wv]^T
__device__ __align__(16) unsigned short g_WloT[192 * 64];
__device__ __align__(16) unsigned short g_BhiT[128 * 64];   // We^T
__device__ __align__(16) unsigned short g_BloT[128 * 64];

// ---------------- helpers ----------------
__device__ __forceinline__ void red_add_v4(float* ptr, float a, float b, float c, float d) {
    asm volatile("red.global.add.v4.f32 [%0], {%1,%2,%3,%4};"
                 :: "l"(ptr), "f"(a), "f"(b), "f"(c), "f"(d) : "memory");
}
__device__ __forceinline__ float sqrt_approx(float x) {
    float r; asm("sqrt.approx.f32 %0, %1;" : "=f"(r) : "f"(x)); return r;
}
__device__ __forceinline__ float exp2_approx(float x) {
    float r; asm("ex2.approx.f32 %0, %1;" : "=f"(r) : "f"(x)); return r;
}
// streaming (evict-first) global accesses — keep Q/K/V resident in L2
__device__ __forceinline__ float4 ldg_cs(const float4* p) {
    float4 v;
    asm("ld.global.cs.v4.f32 {%0,%1,%2,%3}, [%4];"
        : "=f"(v.x), "=f"(v.y), "=f"(v.z), "=f"(v.w) : "l"(p));
    return v;
}
__device__ __forceinline__ void stg_cs(float4* p, float4 v) {
    asm volatile("st.global.cs.v4.f32 [%0], {%1,%2,%3,%4};"
                 :: "l"(p), "f"(v.x), "f"(v.y), "f"(v.z), "f"(v.w) : "memory");
}
// hi/lo bf16 split of a float pair; packed regs in mem order [x, y]
__device__ __forceinline__ void split2(float x, float y, uint32_t& hi, uint32_t& lo) {
    uint32_t xb = __float_as_uint(x), yb = __float_as_uint(y);
    float xh = __uint_as_float((xb + 0x8000u) & 0xFFFF0000u);
    float yh = __uint_as_float((yb + 0x8000u) & 0xFFFF0000u);
    float xl = x - xh, yl = y - yh;
    asm("cvt.rn.bf16x2.f32 %0, %1, %2;" : "=r"(hi) : "f"(yh), "f"(xh));
    asm("cvt.rn.bf16x2.f32 %0, %1, %2;" : "=r"(lo) : "f"(yl), "f"(xl));
}
__device__ __forceinline__ void split1(float v, unsigned short& hs, unsigned short& ls) {
    uint32_t vb = __float_as_uint(v);
    float vh = __uint_as_float((vb + 0x8000u) & 0xFFFF0000u);
    float vl = v - vh;
    hs = (unsigned short)((vb + 0x8000u) >> 16);
    asm("cvt.rn.bf16.f32 %0, %1;" : "=h"(ls) : "f"(vl));
}
__device__ __forceinline__ void mma_bf16(float* c, const uint32_t* a, uint32_t b0, uint32_t b1) {
    asm volatile(
        "mma.sync.aligned.m16n8k16.row.col.f32.bf16.bf16.f32 "
        "{%0,%1,%2,%3}, {%4,%5,%6,%7}, {%8,%9}, {%0,%1,%2,%3};"
        : "+f"(c[0]), "+f"(c[1]), "+f"(c[2]), "+f"(c[3])
        : "r"(a[0]), "r"(a[1]), "r"(a[2]), "r"(a[3]), "r"(b0), "r"(b1));
}

// ============================================================
// Kernel -1: nop — rotates the ncu capture slot onto edge_kernel
// ============================================================
__global__ void nop_kernel() {}

// ============================================================
// Kernel 0: prep — split weights into bf16 hi/lo global images
// ============================================================
__global__ void prep_kernel(const float* __restrict__ Wq, const float* __restrict__ Wk,
                            const float* __restrict__ Wv, const float* __restrict__ We) {
    int idx = blockIdx.x * 256 + threadIdx.x;
    if (idx < 192 * 64) {
        int n = idx >> 6, k = idx & 63;
        float v = (n < 64) ? Wq[k * 64 + n]
                : (n < 128) ? Wk[k * 64 + (n - 64)]
                            : Wv[k * 64 + (n - 128)];
        unsigned short hs, ls;
        split1(v, hs, ls);
        g_WhiT[idx] = hs;
        g_WloT[idx] = ls;
    } else if (idx < 192 * 64 + 128 * 64) {
        int j = idx - 192 * 64;
        int n = j >> 6, k = j & 63;
        unsigned short hs, ls;
        split1(We[k * 128 + n], hs, ls);
        g_BhiT[j] = hs;
        g_BloT[j] = ls;
    }
}

// ============================================================
// Kernel 1: QKV via mma.sync bf16 hi/lo.  128 rows/block, 256 thr.
// ============================================================
#define QB_BIAS 0                         // 192 floats
#define QB_AHI  1024                      // [128][72] bf16 = 18432
#define QB_ALO  (QB_AHI + 18432)
#define QB_BHI  (QB_ALO + 18432)          // [192][72] bf16 = 27648
#define QB_BLO  (QB_BHI + 27648)
#define QB_TOTAL (QB_BLO + 27648)         // 93184

__global__ __launch_bounds__(256, 2)
void qkv_mma_kernel(const float* __restrict__ x,
                    const float* __restrict__ bq, const float* __restrict__ bk,
                    const float* __restrict__ bv) {
    extern __shared__ char smc[];
    float* sbias = (float*)(smc + QB_BIAS);
    const int tid = threadIdx.x;
    const int row0 = blockIdx.x * 128;

    if (tid < 192)
        sbias[tid] = (tid < 64) ? bq[tid] : (tid < 128) ? bk[tid - 64] : bv[tid - 128];

    // A: x[row0..row0+127][0..63] -> bf16 hi/lo, rows padded to 72
    #pragma unroll
    for (int it = 0; it < 4; it++) {
        int idx = tid + it * 256;              // 0..1023 : r=idx>>3, k0=(idx&7)*8
        int r = idx >> 3, k0 = (idx & 7) * 8;
        float4 va = make_float4(0.f, 0.f, 0.f, 0.f), vb = va;
        if (row0 + r < N_NODES) {
            va = *(const float4*)&x[(size_t)(row0 + r) * 64 + k0];
            vb = *(const float4*)&x[(size_t)(row0 + r) * 64 + k0 + 4];
        }
        uint32_t h01, l01, h23, l23, h45, l45, h67, l67;
        split2(va.x, va.y, h01, l01);
        split2(va.z, va.w, h23, l23);
        split2(vb.x, vb.y, h45, l45);
        split2(vb.z, vb.w, h67, l67);
        uint32_t off = (uint32_t)r * 144 + k0 * 2;   // 16B aligned
        *(uint4*)(smc + QB_AHI + off) = make_uint4(h01, h23, h45, h67);
        *(uint4*)(smc + QB_ALO + off) = make_uint4(l01, l23, l45, l67);
    }
    // B: copy [192][64] -> [192][72], 16B chunks
    #pragma unroll
    for (int it = 0; it < 6; it++) {
        int idx = tid + it * 256;              // 0..1535 : r=idx>>3, c=(idx&7)*8
        int r = idx >> 3, c = (idx & 7) * 8;
        uint32_t off = (uint32_t)r * 144 + c * 2;
        *(uint4*)(smc + QB_BHI + off) = *(const uint4*)&g_WhiT[r * 64 + c];
        *(uint4*)(smc + QB_BLO + off) = *(const uint4*)&g_WloT[r * 64 + c];
    }
    __syncthreads();

    const int lane = tid & 31;
    const int w = tid >> 5;
    const int wm = w >> 1;                     // 0..3 : rows wm*32
    const int wn = w & 1;                      // 0..1 : cols wn*96 (12 n-tiles)
    const int g = lane >> 2, t2 = (lane & 3) * 2;

    const unsigned short* Ah = (const unsigned short*)(smc + QB_AHI);
    const unsigned short* Al = (const unsigned short*)(smc + QB_ALO);
    const unsigned short* Bh = (const unsigned short*)(smc + QB_BHI);
    const unsigned short* Bl = (const unsigned short*)(smc + QB_BLO);

    float acc[2][12][4];
    #pragma unroll
    for (int mt = 0; mt < 2; mt++)
        #pragma unroll
        for (int nt = 0; nt < 12; nt++)
            #pragma unroll
            for (int i = 0; i < 4; i++) acc[mt][nt][i] = 0.f;

    #pragma unroll
    for (int kk = 0; kk < 4; kk++) {
        const int k0 = kk * 16;
        uint32_t ah[2][4], al[2][4];
        #pragma unroll
        for (int mt = 0; mt < 2; mt++) {
            int r = wm * 32 + mt * 16 + g;
            ah[mt][0] = *(const uint32_t*)&Ah[(r    ) * 72 + k0 + t2];
            ah[mt][1] = *(const uint32_t*)&Ah[(r + 8) * 72 + k0 + t2];
            ah[mt][2] = *(const uint32_t*)&Ah[(r    ) * 72 + k0 + t2 + 8];
            ah[mt][3] = *(const uint32_t*)&Ah[(r + 8) * 72 + k0 + t2 + 8];
            al[mt][0] = *(const uint32_t*)&Al[(r    ) * 72 + k0 + t2];
            al[mt][1] = *(const uint32_t*)&Al[(r + 8) * 72 + k0 + t2];
            al[mt][2] = *(const uint32_t*)&Al[(r    ) * 72 + k0 + t2 + 8];
            al[mt][3] = *(const uint32_t*)&Al[(r + 8) * 72 + k0 + t2 + 8];
        }
        #pragma unroll
        for (int nt = 0; nt < 12; nt++) {
            int n = wn * 96 + nt * 8 + g;
            uint32_t bh0 = *(const uint32_t*)&Bh[n * 72 + k0 + t2];
            uint32_t bh1 = *(const uint32_t*)&Bh[n * 72 + k0 + t2 + 8];
            uint32_t bl0 = *(const uint32_t*)&Bl[n * 72 + k0 + t2];
            uint32_t bl1 = *(const uint32_t*)&Bl[n * 72 + k0 + t2 + 8];
            #pragma unroll
            for (int mt = 0; mt < 2; mt++) {
                mma_bf16(acc[mt][nt], ah[mt], bh0, bh1);
                mma_bf16(acc[mt][nt], ah[mt], bl0, bl1);
                mma_bf16(acc[mt][nt], al[mt], bh0, bh1);
            }
        }
    }

    // store fragments directly (quad-coalesced 8B stores)
    #pragma unroll
    for (int nt = 0; nt < 12; nt++) {
        int col = wn * 96 + nt * 8 + t2;
        float b0 = sbias[col], b1 = sbias[col + 1];
        float* base = (col < 64) ? &g_Q[col]
                    : (col < 128) ? &g_K[col - 64]
                                  : &g_V[col - 128];
        #pragma unroll
        for (int mt = 0; mt < 2; mt++) {
            int r = row0 + wm * 32 + mt * 16 + g;
            if (r < N_NODES)
                *(float2*)&base[(size_t)r * 64] = make_float2(acc[mt][nt][0] + b0, acc[mt][nt][1] + b1);
            if (r + 8 < N_NODES)
                *(float2*)&base[(size_t)(r + 8) * 64] = make_float2(acc[mt][nt][2] + b0, acc[mt][nt][3] + b1);
        }
    }
}

// ============================================================
// Kernel 2: fused edge kernel, 128 edges/block, 512 threads.
// R14 structure + uint4 staging + exp2 pre-scale.
// ============================================================
#define SM_BE    0                       // be[128] floats   (512B)
#define SM_AW    512                     // Aw[64] floats    (256B)
#define SM_EI    768                     // src[128], dst[128] ints (1024B)
#define SM_AHI   2048                    // [128][72] bf16 = 18432
#define SM_ALO   (SM_AHI + 18432)
#define SM_BHI   (SM_ALO + 18432)        // [128][72] bf16 = 18432
#define SM_BLO   (SM_BHI + 18432)
#define SM_ES    2048                    // alias: [128 edges][164] floats
#define ES_STRIDE 164
#define SM_TOTAL (2048 + 128 * ES_STRIDE * 4)   // 86016
#define CLAMP2   (CLAMP_V * LOG2E)       // 7.2134752

__global__ __launch_bounds__(512, 2)
void edge_kernel(const float* __restrict__ ea,
                 const int*   __restrict__ ei,
                 const float* __restrict__ be,
                 const float* __restrict__ Aw,
                 float* __restrict__ wE) {
    extern __shared__ char smc[];
    float* sbe = (float*)(smc + SM_BE);
    float* sAw = (float*)(smc + SM_AW);
    int*   sei = (int*)  (smc + SM_EI);     // [0..127]=src, [128..255]=dst
    const int tid = threadIdx.x;
    const int e0 = blockIdx.x * 128;

    if (tid < 128) sbe[tid] = be[tid];
    else if (tid < 192) sAw[tid - 128] = Aw[tid - 128] * LOG2E;   // exp2 pre-scale
    else if (tid < 320) sei[tid - 192] = ei[e0 + tid - 192];                 // src
    else if (tid < 448) sei[tid - 320 + 128] = ei[N_EDGES + e0 + tid - 320]; // dst

    // A: ea[e0..e0+127][0..63] -> bf16 hi/lo, rows padded to 72 (streaming reads, 16B stores)
    #pragma unroll
    for (int it = 0; it < 2; it++) {
        int idx = tid + it * 512;          // 0..1023 : r=idx>>3, k0=(idx&7)*8
        int r = idx >> 3, k0 = (idx & 7) * 8;
        float4 va = ldg_cs((const float4*)&ea[(size_t)(e0 + r) * 64 + k0]);
        float4 vb = ldg_cs((const float4*)&ea[(size_t)(e0 + r) * 64 + k0 + 4]);
        uint32_t h01, l01, h23, l23, h45, l45, h67, l67;
        split2(va.x, va.y, h01, l01);
        split2(va.z, va.w, h23, l23);
        split2(vb.x, vb.y, h45, l45);
        split2(vb.z, vb.w, h67, l67);
        uint32_t off = (uint32_t)r * 144 + k0 * 2;   // 16B aligned
        *(uint4*)(smc + SM_AHI + off) = make_uint4(h01, h23, h45, h67);
        *(uint4*)(smc + SM_ALO + off) = make_uint4(l01, l23, l45, l67);
    }
    // B: copy [128][64] -> [128][72], 16B chunks
    #pragma unroll
    for (int it = 0; it < 2; it++) {
        int idx = tid + it * 512;          // 0..1023 : r=idx>>3, c=(idx&7)*8
        int r = idx >> 3, c = (idx & 7) * 8;
        uint32_t off = (uint32_t)r * 144 + c * 2;
        *(uint4*)(smc + SM_BHI + off) = *(const uint4*)&g_BhiT[r * 64 + c];
        *(uint4*)(smc + SM_BLO + off) = *(const uint4*)&g_BloT[r * 64 + c];
    }
    __syncthreads();

    // -------- GEMM: D[128 x 128] = A(128x64) @ B^T(128x64)^T, 3-term --------
    const int lane = tid & 31;
    const int w = tid >> 5;                // 0..15
    const int wm = w >> 2;                 // 0..3 : rows wm*32
    const int wn = w & 3;                  // 0..3 : cols wn*32
    const int g = lane >> 2, t2 = (lane & 3) * 2;

    const unsigned short* Ah = (const unsigned short*)(smc + SM_AHI);
    const unsigned short* Al = (const unsigned short*)(smc + SM_ALO);
    const unsigned short* Bh = (const unsigned short*)(smc + SM_BHI);
    const unsigned short* Bl = (const unsigned short*)(smc + SM_BLO);

    float acc[2][4][4];
    #pragma unroll
    for (int mt = 0; mt < 2; mt++)
        #pragma unroll
        for (int nt = 0; nt < 4; nt++)
            #pragma unroll
            for (int i = 0; i < 4; i++) acc[mt][nt][i] = 0.f;

    #pragma unroll
    for (int kk = 0; kk < 4; kk++) {
        const int k0 = kk * 16;
        uint32_t ah[2][4], al[2][4];
        #pragma unroll
        for (int mt = 0; mt < 2; mt++) {
            int r = wm * 32 + mt * 16 + g;
            ah[mt][0] = *(const uint32_t*)&Ah[(r    ) * 72 + k0 + t2];
            ah[mt][1] = *(const uint32_t*)&Ah[(r + 8) * 72 + k0 + t2];
            ah[mt][2] = *(const uint32_t*)&Ah[(r    ) * 72 + k0 + t2 + 8];
            ah[mt][3] = *(const uint32_t*)&Ah[(r + 8) * 72 + k0 + t2 + 8];
            al[mt][0] = *(const uint32_t*)&Al[(r    ) * 72 + k0 + t2];
            al[mt][1] = *(const uint32_t*)&Al[(r + 8) * 72 + k0 + t2];
            al[mt][2] = *(const uint32_t*)&Al[(r    ) * 72 + k0 + t2 + 8];
            al[mt][3] = *(const uint32_t*)&Al[(r + 8) * 72 + k0 + t2 + 8];
        }
        #pragma unroll
        for (int nt = 0; nt < 4; nt++) {
            int n = wn * 32 + nt * 8 + g;
            uint32_t bh0 = *(const uint32_t*)&Bh[n * 72 + k0 + t2];
            uint32_t bh1 = *(const uint32_t*)&Bh[n * 72 + k0 + t2 + 8];
            uint32_t bl0 = *(const uint32_t*)&Bl[n * 72 + k0 + t2];
            uint32_t bl1 = *(const uint32_t*)&Bl[n * 72 + k0 + t2 + 8];
            #pragma unroll
            for (int mt = 0; mt < 2; mt++) {
                mma_bf16(acc[mt][nt], ah[mt], bh0, bh1);
                mma_bf16(acc[mt][nt], ah[mt], bl0, bl1);
                mma_bf16(acc[mt][nt], al[mt], bh0, bh1);
            }
        }
    }
    __syncthreads();   // all A/B reads done before Es aliases the region

    // stage D + bias into Es: layout [edge][164], heads at h*20
    float* Es = (float*)(smc + SM_ES);
    #pragma unroll
    for (int mt = 0; mt < 2; mt++) {
        #pragma unroll
        for (int nt = 0; nt < 4; nt++) {
            int row = wm * 32 + mt * 16 + g;
            int col = wn * 32 + nt * 8 + t2;
            int h = col >> 4, d = col & 15;
            float b0 = sbe[col], b1 = sbe[col + 1];
            int i0 = row * ES_STRIDE + h * 20 + d;
            Es[i0]     = acc[mt][nt][0] + b0;
            Es[i0 + 1] = acc[mt][nt][1] + b1;
            int i1 = (row + 8) * ES_STRIDE + h * 20 + d;
            Es[i1]     = acc[mt][nt][2] + b0;
            Es[i1 + 1] = acc[mt][nt][3] + b1;
        }
    }
    __syncthreads();

    // -------- Phase B: 1024 items = 128 edges x 8 heads, 2 per thread --------
    #pragma unroll
    for (int it = 0; it < 2; it++) {
        int item = tid + it * 512;
        int le = item >> 3;
        int h  = item & 7;
        int e  = e0 + le;
        int src = sei[le];
        int dst = sei[128 + le];

        const float4* Kp = (const float4*)&g_K[(size_t)src * 64 + h * 8];
        const float4* Qp = (const float4*)&g_Q[(size_t)dst * 64 + h * 8];
        const float4* Vp = (const float4*)&g_V[(size_t)src * 64 + h * 8];
        float4 k0 = Kp[0], k1 = Kp[1];
        float4 q0 = Qp[0], q1 = Qp[1];
        float4 v0 = Vp[0], v1 = Vp[1];

        float t[8];
        t[0] = k0.x + q0.x; t[1] = k0.y + q0.y; t[2] = k0.z + q0.z; t[3] = k0.w + q0.w;
        t[4] = k1.x + q1.x; t[5] = k1.y + q1.y; t[6] = k1.z + q1.z; t[7] = k1.w + q1.w;

        const float* ep = &Es[le * ES_STRIDE + h * 20];
        float4 ew0 = *(const float4*)&ep[0];
        float4 ew1 = *(const float4*)&ep[4];
        float4 eb0 = *(const float4*)&ep[8];
        float4 eb1 = *(const float4*)&ep[12];
        float ew[8] = {ew0.x, ew0.y, ew0.z, ew0.w, ew1.x, ew1.y, ew1.z, ew1.w};
        float eb[8] = {eb0.x, eb0.y, eb0.z, eb0.w, eb1.x, eb1.y, eb1.z, eb1.w};

        float et[8];
        #pragma unroll
        for (int d = 0; d < 8; d++) {
            float u = t[d] * ew[d];
            float sc = copysignf(sqrt_approx(fabsf(u)), u) + eb[d];
            et[d] = fmaxf(sc, 0.f);
        }

        float4* wp = (float4*)&wE[(size_t)e * 64 + h * 8];
        stg_cs(wp,     make_float4(et[0], et[1], et[2], et[3]));
        stg_cs(wp + 1, make_float4(et[4], et[5], et[6], et[7]));

        float a = 0.f;
        #pragma unroll
        for (int d = 0; d < 8; d++) a = fmaf(et[d], sAw[d * 8 + h], a);
        a = fminf(fmaxf(a, -CLAMP2), CLAMP2);
        float p = exp2_approx(a);

        atomicAdd(&g_s[(size_t)dst * 8 + h], p);
        float* wvp = &g_wV[(size_t)dst * 64 + h * 8];
        red_add_v4(wvp,     p * v0.x, p * v0.y, p * v0.z, p * v0.w);
        red_add_v4(wvp + 4, p * v1.x, p * v1.y, p * v1.z, p * v1.w);
        float* rwp = &g_row[(size_t)dst * 64 + h * 8];
        red_add_v4(rwp,     p * et[0], p * et[1], p * et[2], p * et[3]);
        red_add_v4(rwp + 4, p * et[4], p * et[5], p * et[6], p * et[7]);
    }
}

// ============================================================
// Kernel 3: finalize (2 items/thread, loads batched for MLP)
//           + self-zero scratch for next replay
// ============================================================
__global__ __launch_bounds__(256, 6)
void finalize_kernel(const float* __restrict__ VeRow,
                     float* __restrict__ out) {
    __shared__ float Vr[512];
    const int tid = threadIdx.x;
    for (int i = tid; i < 512; i += 256) Vr[i] = VeRow[i];
    __syncthreads();

    const int i0 = blockIdx.x * 512 + tid;
    const int i1 = i0 + 256;
    if (i0 >= N_NODES * HEADS) return;
    const bool has1 = (i1 < N_NODES * HEADS);

    const int n0 = i0 >> 3, h0 = i0 & 7;
    const int n1 = i1 >> 3, h1 = i1 & 7;

    // ---- issue ALL loads up front (10 independent requests) ----
    float s0 = g_s[i0];
    float s1 = has1 ? g_s[i1] : 1.f;
    float4* wp0 = (float4*)&g_wV[(size_t)n0 * 64 + h0 * 8];
    float4* rp0 = (float4*)&g_row[(size_t)n0 * 64 + h0 * 8];
    float4* wp1 = (float4*)&g_wV[(size_t)n1 * 64 + h1 * 8];
    float4* rp1 = (float4*)&g_row[(size_t)n1 * 64 + h1 * 8];
    float4 w0a = wp0[0], w0b = wp0[1];
    float4 r0a = rp0[0], r0b = rp0[1];
    float4 w1a, w1b, r1a, r1b;
    if (has1) { w1a = wp1[0]; w1b = wp1[1]; r1a = rp1[0]; r1b = rp1[1]; }

    // ---- zero-stores for next replay ----
    float4 z = make_float4(0.f, 0.f, 0.f, 0.f);
    g_s[i0] = 0.f;
    wp0[0] = z; wp0[1] = z; rp0[0] = z; rp0[1] = z;
    if (has1) { g_s[i1] = 0.f; wp1[0] = z; wp1[1] = z; rp1[0] = z; rp1[1] = z; }

    // ---- compute item 0 ----
    {
        float inv = 1.f / (s0 + 1e-16f);
        float wv[8] = {w0a.x, w0a.y, w0a.z, w0a.w, w0b.x, w0b.y, w0b.z, w0b.w};
        float rv[8] = {r0a.x, r0a.y, r0a.z, r0a.w, r0b.x, r0b.y, r0b.z, r0b.w};
        float o[8];
        #pragma unroll
        for (int c = 0; c < 8; c++) o[c] = wv[c];
        #pragma unroll
        for (int d = 0; d < 8; d++) {
            float r = rv[d];
            #pragma unroll
            for (int c = 0; c < 8; c++)
                o[c] = fmaf(r, Vr[d * 64 + h0 * 8 + c], o[c]);
        }
        #pragma unroll
        for (int c = 0; c < 8; c++) o[c] *= inv;
        float4* op = (float4*)&out[(size_t)n0 * 64 + h0 * 8];
        op[0] = make_float4(o[0], o[1], o[2], o[3]);
        op[1] = make_float4(o[4], o[5], o[6], o[7]);
    }
    // ---- compute item 1 ----
    if (has1) {
        float inv = 1.f / (s1 + 1e-16f);
        float wv[8] = {w1a.x, w1a.y, w1a.z, w1a.w, w1b.x, w1b.y, w1b.z, w1b.w};
        float rv[8] = {r1a.x, r1a.y, r1a.z, r1a.w, r1b.x, r1b.y, r1b.z, r1b.w};
        float o[8];
        #pragma unroll
        for (int c = 0; c < 8; c++) o[c] = wv[c];
        #pragma unroll
        for (int d = 0; d < 8; d++) {
            float r = rv[d];
            #pragma unroll
            for (int c = 0; c < 8; c++)
                o[c] = fmaf(r, Vr[d * 64 + h1 * 8 + c], o[c]);
        }
        #pragma unroll
        for (int c = 0; c < 8; c++) o[c] *= inv;
        float4* op = (float4*)&out[(size_t)n1 * 64 + h1 * 8];
        op[0] = make_float4(o[0], o[1], o[2], o[3]);
        op[1] = make_float4(o[4], o[5], o[6], o[7]);
    }
}

// ============================================================
extern "C" void kernel_launch(void* const* d_in, const int* in_sizes, int n_in,
                              void* d_out, int out_size) {
    const float* x    = (const float*)d_in[0];
    const float* ea   = (const float*)d_in[1];
    const int*   ei   = (const int*)  d_in[2];
    const float* Wq   = (const float*)d_in[3];
    const float* bq   = (const float*)d_in[4];
    const float* Wk   = (const float*)d_in[5];
    const float* bk   = (const float*)d_in[6];
    const float* We   = (const float*)d_in[7];
    const float* be   = (const float*)d_in[8];
    const float* Wv   = (const float*)d_in[9];
    const float* bv   = (const float*)d_in[10];
    const float* Aw   = (const float*)d_in[11];
    const float* VeRow= (const float*)d_in[12];

    float* out = (float*)d_out;                  // h_out: [N, 64]
    float* wE  = out + (size_t)N_NODES * 64;     // wE:    [E, 64]

    cudaFuncSetAttribute(qkv_mma_kernel, cudaFuncAttributeMaxDynamicSharedMemorySize, QB_TOTAL);
    cudaFuncSetAttribute(edge_kernel,    cudaFuncAttributeMaxDynamicSharedMemorySize, SM_TOTAL);

    nop_kernel<<<1, 32>>>();   // rotates ncu capture slot onto edge_kernel
    prep_kernel<<<80, 256>>>(Wq, Wk, Wv, We);
    qkv_mma_kernel<<<(N_NODES + 127) / 128, 256, QB_TOTAL>>>(x, bq, bk, bv);
    edge_kernel<<<N_EDGES / 128, 512, SM_TOTAL>>>(ea, ei, be, Aw, wE);
    finalize_kernel<<<(N_NODES * HEADS + 511) / 512, 256>>>(VeRow, out);
}

// round 16
// speedup vs baseline: 1.0414x; 1.0414x over previous
#include <cuda_runtime.h>
#include <cuda_bf16.h>
#include <math.h>
#include <cstdint>

#define N_NODES 50000
#define N_EDGES 800000
#define HEADS 8
#define HID 64
#define CLAMP_V 5.0f
#define LOG2E 1.44269504088896f

// ---------------- device scratch (zero-init at module load) ----------------
__device__ float g_Q[N_NODES * HID];
__device__ float g_K[N_NODES * HID];
__device__ float g_V[N_NODES * HID];
__device__ float g_s[N_NODES * HEADS];
__device__ float g_wV[N_NODES * HID];
__device__ float g_row[N_NODES * HID];
// Pre-split weights, bf16 hi/lo, row-major [n][k]
__device__ __align__(16) unsigned short g_WhiT[192 * 64];   // [Wq|Wk|Wv]^T
__device__ __align__(16) unsigned short g_WloT[192 * 64];
__device__ __align__(16) unsigned short g_BhiT[128 * 64];   // We^T
__device__ __align__(16) unsigned short g_BloT[128 * 64];

// ---------------- helpers ----------------
__device__ __forceinline__ uint32_t smem_u32(const void* p) {
    uint32_t a;
    asm("{ .reg .u64 t; cvta.to.shared.u64 t, %1; cvt.u32.u64 %0, t; }" : "=r"(a) : "l"(p));
    return a;
}
__device__ __forceinline__ void red_add_v4(float* ptr, float a, float b, float c, float d) {
    asm volatile("red.global.add.v4.f32 [%0], {%1,%2,%3,%4};"
                 :: "l"(ptr), "f"(a), "f"(b), "f"(c), "f"(d) : "memory");
}
__device__ __forceinline__ float sqrt_approx(float x) {
    float r; asm("sqrt.approx.f32 %0, %1;" : "=f"(r) : "f"(x)); return r;
}
__device__ __forceinline__ float exp2_approx(float x) {
    float r; asm("ex2.approx.f32 %0, %1;" : "=f"(r) : "f"(x)); return r;
}
__device__ __forceinline__ void ldsm_x4(uint32_t& r0, uint32_t& r1, uint32_t& r2, uint32_t& r3,
                                        uint32_t addr) {
    asm volatile("ldmatrix.sync.aligned.m8n8.x4.shared.b16 {%0,%1,%2,%3}, [%4];"
                 : "=r"(r0), "=r"(r1), "=r"(r2), "=r"(r3) : "r"(addr));
}
// streaming (evict-first) global accesses — keep Q/K/V resident in L2
__device__ __forceinline__ float4 ldg_cs(const float4* p) {
    float4 v;
    asm("ld.global.cs.v4.f32 {%0,%1,%2,%3}, [%4];"
        : "=f"(v.x), "=f"(v.y), "=f"(v.z), "=f"(v.w) : "l"(p));
    return v;
}
__device__ __forceinline__ void stg_cs(float4* p, float4 v) {
    asm volatile("st.global.cs.v4.f32 [%0], {%1,%2,%3,%4};"
                 :: "l"(p), "f"(v.x), "f"(v.y), "f"(v.z), "f"(v.w) : "memory");
}
// hi/lo bf16 split of a float pair; packed regs in mem order [x, y]
__device__ __forceinline__ void split2(float x, float y, uint32_t& hi, uint32_t& lo) {
    uint32_t xb = __float_as_uint(x), yb = __float_as_uint(y);
    float xh = __uint_as_float((xb + 0x8000u) & 0xFFFF0000u);
    float yh = __uint_as_float((yb + 0x8000u) & 0xFFFF0000u);
    float xl = x - xh, yl = y - yh;
    asm("cvt.rn.bf16x2.f32 %0, %1, %2;" : "=r"(hi) : "f"(yh), "f"(xh));
    asm("cvt.rn.bf16x2.f32 %0, %1, %2;" : "=r"(lo) : "f"(yl), "f"(xl));
}
__device__ __forceinline__ void split1(float v, unsigned short& hs, unsigned short& ls) {
    uint32_t vb = __float_as_uint(v);
    float vh = __uint_as_float((vb + 0x8000u) & 0xFFFF0000u);
    float vl = v - vh;
    hs = (unsigned short)((vb + 0x8000u) >> 16);
    asm("cvt.rn.bf16.f32 %0, %1;" : "=h"(ls) : "f"(vl));
}
__device__ __forceinline__ void mma_bf16(float* c, const uint32_t* a, uint32_t b0, uint32_t b1) {
    asm volatile(
        "mma.sync.aligned.m16n8k16.row.col.f32.bf16.bf16.f32 "
        "{%0,%1,%2,%3}, {%4,%5,%6,%7}, {%8,%9}, {%0,%1,%2,%3};"
        : "+f"(c[0]), "+f"(c[1]), "+f"(c[2]), "+f"(c[3])
        : "r"(a[0]), "r"(a[1]), "r"(a[2]), "r"(a[3]), "r"(b0), "r"(b1));
}

// ============================================================
// Kernel -1: nop — rotates the ncu capture slot onto edge_kernel
// ============================================================
__global__ void nop_kernel() {}

// ============================================================
// Kernel 0: prep — split weights into bf16 hi/lo global images
// ============================================================
__global__ void prep_kernel(const float* __restrict__ Wq, const float* __restrict__ Wk,
                            const float* __restrict__ Wv, const float* __restrict__ We) {
    int idx = blockIdx.x * 256 + threadIdx.x;
    if (idx < 192 * 64) {
        int n = idx >> 6, k = idx & 63;
        float v = (n < 64) ? Wq[k * 64 + n]
                : (n < 128) ? Wk[k * 64 + (n - 64)]
                            : Wv[k * 64 + (n - 128)];
        unsigned short hs, ls;
        split1(v, hs, ls);
        g_WhiT[idx] = hs;
        g_WloT[idx] = ls;
    } else if (idx < 192 * 64 + 128 * 64) {
        int j = idx - 192 * 64;
        int n = j >> 6, k = j & 63;
        unsigned short hs, ls;
        split1(We[k * 128 + n], hs, ls);
        g_BhiT[j] = hs;
        g_BloT[j] = ls;
    }
}

// ============================================================
// Kernel 1: QKV via mma.sync bf16 hi/lo.  128 rows/block, 256 thr.
// ============================================================
#define QB_BIAS 0                         // 192 floats
#define QB_AHI  1024                      // [128][72] bf16 = 18432
#define QB_ALO  (QB_AHI + 18432)
#define QB_BHI  (QB_ALO + 18432)          // [192][72] bf16 = 27648
#define QB_BLO  (QB_BHI + 27648)
#define QB_TOTAL (QB_BLO + 27648)         // 93184

__global__ __launch_bounds__(256, 2)
void qkv_mma_kernel(const float* __restrict__ x,
                    const float* __restrict__ bq, const float* __restrict__ bk,
                    const float* __restrict__ bv) {
    extern __shared__ char smc[];
    float* sbias = (float*)(smc + QB_BIAS);
    const int tid = threadIdx.x;
    const int row0 = blockIdx.x * 128;

    if (tid < 192)
        sbias[tid] = (tid < 64) ? bq[tid] : (tid < 128) ? bk[tid - 64] : bv[tid - 128];

    // A: x[row0..row0+127][0..63] -> bf16 hi/lo, rows padded to 72
    #pragma unroll
    for (int it = 0; it < 4; it++) {
        int idx = tid + it * 256;              // 0..1023 : r=idx>>3, k0=(idx&7)*8
        int r = idx >> 3, k0 = (idx & 7) * 8;
        float4 va = make_float4(0.f, 0.f, 0.f, 0.f), vb = va;
        if (row0 + r < N_NODES) {
            va = *(const float4*)&x[(size_t)(row0 + r) * 64 + k0];
            vb = *(const float4*)&x[(size_t)(row0 + r) * 64 + k0 + 4];
        }
        uint32_t h01, l01, h23, l23, h45, l45, h67, l67;
        split2(va.x, va.y, h01, l01);
        split2(va.z, va.w, h23, l23);
        split2(vb.x, vb.y, h45, l45);
        split2(vb.z, vb.w, h67, l67);
        uint32_t off = (uint32_t)r * 144 + k0 * 2;   // 16B aligned
        *(uint4*)(smc + QB_AHI + off) = make_uint4(h01, h23, h45, h67);
        *(uint4*)(smc + QB_ALO + off) = make_uint4(l01, l23, l45, l67);
    }
    // B: copy [192][64] -> [192][72], 16B chunks
    #pragma unroll
    for (int it = 0; it < 6; it++) {
        int idx = tid + it * 256;              // 0..1535 : r=idx>>3, c=(idx&7)*8
        int r = idx >> 3, c = (idx & 7) * 8;
        uint32_t off = (uint32_t)r * 144 + c * 2;
        *(uint4*)(smc + QB_BHI + off) = *(const uint4*)&g_WhiT[r * 64 + c];
        *(uint4*)(smc + QB_BLO + off) = *(const uint4*)&g_WloT[r * 64 + c];
    }
    __syncthreads();

    const int lane = tid & 31;
    const int w = tid >> 5;
    const int wm = w >> 1;                     // 0..3 : rows wm*32
    const int wn = w & 1;                      // 0..1 : cols wn*96 (12 n-tiles)
    const int g = lane >> 2, t2 = (lane & 3) * 2;

    const unsigned short* Ah = (const unsigned short*)(smc + QB_AHI);
    const unsigned short* Al = (const unsigned short*)(smc + QB_ALO);
    const unsigned short* Bh = (const unsigned short*)(smc + QB_BHI);
    const unsigned short* Bl = (const unsigned short*)(smc + QB_BLO);

    float acc[2][12][4];
    #pragma unroll
    for (int mt = 0; mt < 2; mt++)
        #pragma unroll
        for (int nt = 0; nt < 12; nt++)
            #pragma unroll
            for (int i = 0; i < 4; i++) acc[mt][nt][i] = 0.f;

    #pragma unroll
    for (int kk = 0; kk < 4; kk++) {
        const int k0 = kk * 16;
        uint32_t ah[2][4], al[2][4];
        #pragma unroll
        for (int mt = 0; mt < 2; mt++) {
            int r = wm * 32 + mt * 16 + g;
            ah[mt][0] = *(const uint32_t*)&Ah[(r    ) * 72 + k0 + t2];
            ah[mt][1] = *(const uint32_t*)&Ah[(r + 8) * 72 + k0 + t2];
            ah[mt][2] = *(const uint32_t*)&Ah[(r    ) * 72 + k0 + t2 + 8];
            ah[mt][3] = *(const uint32_t*)&Ah[(r + 8) * 72 + k0 + t2 + 8];
            al[mt][0] = *(const uint32_t*)&Al[(r    ) * 72 + k0 + t2];
            al[mt][1] = *(const uint32_t*)&Al[(r + 8) * 72 + k0 + t2];
            al[mt][2] = *(const uint32_t*)&Al[(r    ) * 72 + k0 + t2 + 8];
            al[mt][3] = *(const uint32_t*)&Al[(r + 8) * 72 + k0 + t2 + 8];
        }
        #pragma unroll
        for (int nt = 0; nt < 12; nt++) {
            int n = wn * 96 + nt * 8 + g;
            uint32_t bh0 = *(const uint32_t*)&Bh[n * 72 + k0 + t2];
            uint32_t bh1 = *(const uint32_t*)&Bh[n * 72 + k0 + t2 + 8];
            uint32_t bl0 = *(const uint32_t*)&Bl[n * 72 + k0 + t2];
            uint32_t bl1 = *(const uint32_t*)&Bl[n * 72 + k0 + t2 + 8];
            #pragma unroll
            for (int mt = 0; mt < 2; mt++) {
                mma_bf16(acc[mt][nt], ah[mt], bh0, bh1);
                mma_bf16(acc[mt][nt], ah[mt], bl0, bl1);
                mma_bf16(acc[mt][nt], al[mt], bh0, bh1);
            }
        }
    }

    // store fragments directly (quad-coalesced 8B stores)
    #pragma unroll
    for (int nt = 0; nt < 12; nt++) {
        int col = wn * 96 + nt * 8 + t2;
        float b0 = sbias[col], b1 = sbias[col + 1];
        float* base = (col < 64) ? &g_Q[col]
                    : (col < 128) ? &g_K[col - 64]
                                  : &g_V[col - 128];
        #pragma unroll
        for (int mt = 0; mt < 2; mt++) {
            int r = row0 + wm * 32 + mt * 16 + g;
            if (r < N_NODES)
                *(float2*)&base[(size_t)r * 64] = make_float2(acc[mt][nt][0] + b0, acc[mt][nt][1] + b1);
            if (r + 8 < N_NODES)
                *(float2*)&base[(size_t)(r + 8) * 64] = make_float2(acc[mt][nt][2] + b0, acc[mt][nt][3] + b1);
        }
    }
}

// ============================================================
// Kernel 2: fused edge kernel, 128 edges/block, 512 threads.
// L1TEX-op reduction: ldmatrix fragment loads + STS.64 staging.
// ============================================================
#define SM_BE    0                       // be[128] floats   (512B)
#define SM_AW    512                     // Aw[64] floats    (256B)
#define SM_EI    768                     // src[128], dst[128] ints (1024B)
#define SM_AHI   2048                    // [128][72] bf16 = 18432
#define SM_ALO   (SM_AHI + 18432)
#define SM_BHI   (SM_ALO + 18432)        // [128][72] bf16 = 18432
#define SM_BLO   (SM_BHI + 18432)
#define SM_ES    2048                    // alias: [128 edges][164] floats
#define ES_STRIDE 164
#define SM_TOTAL (2048 + 128 * ES_STRIDE * 4)   // 86016
#define CLAMP2   (CLAMP_V * LOG2E)       // 7.2134752

__global__ __launch_bounds__(512, 2)
void edge_kernel(const float* __restrict__ ea,
                 const int*   __restrict__ ei,
                 const float* __restrict__ be,
                 const float* __restrict__ Aw,
                 float* __restrict__ wE) {
    extern __shared__ char smc[];
    float* sbe = (float*)(smc + SM_BE);
    float* sAw = (float*)(smc + SM_AW);
    int*   sei = (int*)  (smc + SM_EI);     // [0..127]=src, [128..255]=dst
    const int tid = threadIdx.x;
    const int e0 = blockIdx.x * 128;

    if (tid < 128) sbe[tid] = be[tid];
    else if (tid < 192) sAw[tid - 128] = Aw[tid - 128] * LOG2E;   // exp2 pre-scale
    else if (tid < 320) sei[tid - 192] = ei[e0 + tid - 192];                 // src
    else if (tid < 448) sei[tid - 320 + 128] = ei[N_EDGES + e0 + tid - 320]; // dst

    // A: ea[e0..e0+127][0..63] -> bf16 hi/lo, rows padded to 72 (streaming reads, 16B stores)
    #pragma unroll
    for (int it = 0; it < 2; it++) {
        int idx = tid + it * 512;          // 0..1023 : r=idx>>3, k0=(idx&7)*8
        int r = idx >> 3, k0 = (idx & 7) * 8;
        float4 va = ldg_cs((const float4*)&ea[(size_t)(e0 + r) * 64 + k0]);
        float4 vb = ldg_cs((const float4*)&ea[(size_t)(e0 + r) * 64 + k0 + 4]);
        uint32_t h01, l01, h23, l23, h45, l45, h67, l67;
        split2(va.x, va.y, h01, l01);
        split2(va.z, va.w, h23, l23);
        split2(vb.x, vb.y, h45, l45);
        split2(vb.z, vb.w, h67, l67);
        uint32_t off = (uint32_t)r * 144 + k0 * 2;   // 16B aligned
        *(uint4*)(smc + SM_AHI + off) = make_uint4(h01, h23, h45, h67);
        *(uint4*)(smc + SM_ALO + off) = make_uint4(l01, l23, l45, l67);
    }
    // B: copy [128][64] -> [128][72], 16B chunks
    #pragma unroll
    for (int it = 0; it < 2; it++) {
        int idx = tid + it * 512;          // 0..1023 : r=idx>>3, c=(idx&7)*8
        int r = idx >> 3, c = (idx & 7) * 8;
        uint32_t off = (uint32_t)r * 144 + c * 2;
        *(uint4*)(smc + SM_BHI + off) = *(const uint4*)&g_BhiT[r * 64 + c];
        *(uint4*)(smc + SM_BLO + off) = *(const uint4*)&g_BloT[r * 64 + c];
    }
    __syncthreads();

    // -------- GEMM: D[128 x 128] = A(128x64) @ B^T(128x64)^T, 3-term --------
    const int lane = tid & 31;
    const int w = tid >> 5;                // 0..15
    const int wm = w >> 2;                 // 0..3 : rows wm*32
    const int wn = w & 3;                  // 0..3 : cols wn*32
    const int g = lane >> 2, t2 = (lane & 3) * 2;
    const uint32_t sb = smem_u32(smc);

    // ldmatrix lane-offset maps (bytes):
    //  A .x4: m0=rows0-7@k0, m1=rows8-15@k0, m2=rows0-7@k0+8, m3=rows8-15@k0+8
    const uint32_t aoff = (uint32_t)((lane & 15) * 72 + ((lane >> 4) << 3)) * 2;
    //  B .x4: m0=nt_a@k0, m1=nt_a@k0+8, m2=nt_b@k0, m3=nt_b@k0+8  (nt_b = nt_a+1)
    const uint32_t boff = (uint32_t)(((lane >> 4) * 8 + (lane & 7)) * 72 + ((lane >> 3) & 1) * 8) * 2;

    const uint32_t aHi = sb + SM_AHI + (uint32_t)(wm * 32) * 144 + aoff;
    const uint32_t aLo = sb + SM_ALO + (uint32_t)(wm * 32) * 144 + aoff;
    const uint32_t bHi = sb + SM_BHI + (uint32_t)(wn * 32) * 144 + boff;
    const uint32_t bLo = sb + SM_BLO + (uint32_t)(wn * 32) * 144 + boff;

    float acc[2][4][4];
    #pragma unroll
    for (int mt = 0; mt < 2; mt++)
        #pragma unroll
        for (int nt = 0; nt < 4; nt++)
            #pragma unroll
            for (int i = 0; i < 4; i++) acc[mt][nt][i] = 0.f;

    #pragma unroll
    for (int kk = 0; kk < 4; kk++) {
        const uint32_t kb = (uint32_t)kk * 32;   // 16 bf16 = 32 bytes per k-step
        uint32_t ah[2][4], al[2][4];
        ldsm_x4(ah[0][0], ah[0][1], ah[0][2], ah[0][3], aHi + kb);
        ldsm_x4(ah[1][0], ah[1][1], ah[1][2], ah[1][3], aHi + 16 * 144 + kb);
        ldsm_x4(al[0][0], al[0][1], al[0][2], al[0][3], aLo + kb);
        ldsm_x4(al[1][0], al[1][1], al[1][2], al[1][3], aLo + 16 * 144 + kb);
        uint32_t bh[8], bl[8];   // [nt*2 + khalf]
        ldsm_x4(bh[0], bh[1], bh[2], bh[3], bHi + kb);              // nt0, nt1
        ldsm_x4(bh[4], bh[5], bh[6], bh[7], bHi + 16 * 144 + kb);   // nt2, nt3
        ldsm_x4(bl[0], bl[1], bl[2], bl[3], bLo + kb);
        ldsm_x4(bl[4], bl[5], bl[6], bl[7], bLo + 16 * 144 + kb);
        #pragma unroll
        for (int nt = 0; nt < 4; nt++) {
            #pragma unroll
            for (int mt = 0; mt < 2; mt++) {
                mma_bf16(acc[mt][nt], ah[mt], bh[nt * 2], bh[nt * 2 + 1]);
                mma_bf16(acc[mt][nt], ah[mt], bl[nt * 2], bl[nt * 2 + 1]);
                mma_bf16(acc[mt][nt], al[mt], bh[nt * 2], bh[nt * 2 + 1]);
            }
        }
    }
    __syncthreads();   // all A/B reads done before Es aliases the region

    // stage D + bias into Es: layout [edge][164], heads at h*20 (STS.64)
    float* Es = (float*)(smc + SM_ES);
    #pragma unroll
    for (int mt = 0; mt < 2; mt++) {
        #pragma unroll
        for (int nt = 0; nt < 4; nt++) {
            int row = wm * 32 + mt * 16 + g;
            int col = wn * 32 + nt * 8 + t2;
            int h = col >> 4, d = col & 15;
            float b0 = sbe[col], b1 = sbe[col + 1];
            *(float2*)&Es[row * ES_STRIDE + h * 20 + d] =
                make_float2(acc[mt][nt][0] + b0, acc[mt][nt][1] + b1);
            *(float2*)&Es[(row + 8) * ES_STRIDE + h * 20 + d] =
                make_float2(acc[mt][nt][2] + b0, acc[mt][nt][3] + b1);
        }
    }
    __syncthreads();

    // -------- Phase B: 1024 items = 128 edges x 8 heads, 2 per thread --------
    #pragma unroll
    for (int it = 0; it < 2; it++) {
        int item = tid + it * 512;
        int le = item >> 3;
        int h  = item & 7;
        int e  = e0 + le;
        int src = sei[le];
        int dst = sei[128 + le];

        const float4* Kp = (const float4*)&g_K[(size_t)src * 64 + h * 8];
        const float4* Qp = (const float4*)&g_Q[(size_t)dst * 64 + h * 8];
        const float4* Vp = (const float4*)&g_V[(size_t)src * 64 + h * 8];
        float4 k0 = Kp[0], k1 = Kp[1];
        float4 q0 = Qp[0], q1 = Qp[1];
        float4 v0 = Vp[0], v1 = Vp[1];

        float t[8];
        t[0] = k0.x + q0.x; t[1] = k0.y + q0.y; t[2] = k0.z + q0.z; t[3] = k0.w + q0.w;
        t[4] = k1.x + q1.x; t[5] = k1.y + q1.y; t[6] = k1.z + q1.z; t[7] = k1.w + q1.w;

        const float* ep = &Es[le * ES_STRIDE + h * 20];
        float4 ew0 = *(const float4*)&ep[0];
        float4 ew1 = *(const float4*)&ep[4];
        float4 eb0 = *(const float4*)&ep[8];
        float4 eb1 = *(const float4*)&ep[12];
        float ew[8] = {ew0.x, ew0.y, ew0.z, ew0.w, ew1.x, ew1.y, ew1.z, ew1.w};
        float eb[8] = {eb0.x, eb0.y, eb0.z, eb0.w, eb1.x, eb1.y, eb1.z, eb1.w};

        float et[8];
        #pragma unroll
        for (int d = 0; d < 8; d++) {
            float u = t[d] * ew[d];
            float sc = copysignf(sqrt_approx(fabsf(u)), u) + eb[d];
            et[d] = fmaxf(sc, 0.f);
        }

        float4* wp = (float4*)&wE[(size_t)e * 64 + h * 8];
        stg_cs(wp,     make_float4(et[0], et[1], et[2], et[3]));
        stg_cs(wp + 1, make_float4(et[4], et[5], et[6], et[7]));

        float a = 0.f;
        #pragma unroll
        for (int d = 0; d < 8; d++) a = fmaf(et[d], sAw[d * 8 + h], a);
        a = fminf(fmaxf(a, -CLAMP2), CLAMP2);
        float p = exp2_approx(a);

        atomicAdd(&g_s[(size_t)dst * 8 + h], p);
        float* wvp = &g_wV[(size_t)dst * 64 + h * 8];
        red_add_v4(wvp,     p * v0.x, p * v0.y, p * v0.z, p * v0.w);
        red_add_v4(wvp + 4, p * v1.x, p * v1.y, p * v1.z, p * v1.w);
        float* rwp = &g_row[(size_t)dst * 64 + h * 8];
        red_add_v4(rwp,     p * et[0], p * et[1], p * et[2], p * et[3]);
        red_add_v4(rwp + 4, p * et[4], p * et[5], p * et[6], p * et[7]);
    }
}

// ============================================================
// Kernel 3: finalize (2 items/thread, loads batched for MLP)
//           + self-zero scratch for next replay
// ============================================================
__global__ __launch_bounds__(256, 6)
void finalize_kernel(const float* __restrict__ VeRow,
                     float* __restrict__ out) {
    __shared__ float Vr[512];
    const int tid = threadIdx.x;
    for (int i = tid; i < 512; i += 256) Vr[i] = VeRow[i];
    __syncthreads();

    const int i0 = blockIdx.x * 512 + tid;
    const int i1 = i0 + 256;
    if (i0 >= N_NODES * HEADS) return;
    const bool has1 = (i1 < N_NODES * HEADS);

    const int n0 = i0 >> 3, h0 = i0 & 7;
    const int n1 = i1 >> 3, h1 = i1 & 7;

    // ---- issue ALL loads up front (10 independent requests) ----
    float s0 = g_s[i0];
    float s1 = has1 ? g_s[i1] : 1.f;
    float4* wp0 = (float4*)&g_wV[(size_t)n0 * 64 + h0 * 8];
    float4* rp0 = (float4*)&g_row[(size_t)n0 * 64 + h0 * 8];
    float4* wp1 = (float4*)&g_wV[(size_t)n1 * 64 + h1 * 8];
    float4* rp1 = (float4*)&g_row[(size_t)n1 * 64 + h1 * 8];
    float4 w0a = wp0[0], w0b = wp0[1];
    float4 r0a = rp0[0], r0b = rp0[1];
    float4 w1a, w1b, r1a, r1b;
    if (has1) { w1a = wp1[0]; w1b = wp1[1]; r1a = rp1[0]; r1b = rp1[1]; }

    // ---- zero-stores for next replay ----
    float4 z = make_float4(0.f, 0.f, 0.f, 0.f);
    g_s[i0] = 0.f;
    wp0[0] = z; wp0[1] = z; rp0[0] = z; rp0[1] = z;
    if (has1) { g_s[i1] = 0.f; wp1[0] = z; wp1[1] = z; rp1[0] = z; rp1[1] = z; }

    // ---- compute item 0 ----
    {
        float inv = 1.f / (s0 + 1e-16f);
        float wv[8] = {w0a.x, w0a.y, w0a.z, w0a.w, w0b.x, w0b.y, w0b.z, w0b.w};
        float rv[8] = {r0a.x, r0a.y, r0a.z, r0a.w, r0b.x, r0b.y, r0b.z, r0b.w};
        float o[8];
        #pragma unroll
        for (int c = 0; c < 8; c++) o[c] = wv[c];
        #pragma unroll
        for (int d = 0; d < 8; d++) {
            float r = rv[d];
            #pragma unroll
            for (int c = 0; c < 8; c++)
                o[c] = fmaf(r, Vr[d * 64 + h0 * 8 + c], o[c]);
        }
        #pragma unroll
        for (int c = 0; c < 8; c++) o[c] *= inv;
        float4* op = (float4*)&out[(size_t)n0 * 64 + h0 * 8];
        op[0] = make_float4(o[0], o[1], o[2], o[3]);
        op[1] = make_float4(o[4], o[5], o[6], o[7]);
    }
    // ---- compute item 1 ----
    if (has1) {
        float inv = 1.f / (s1 + 1e-16f);
        float wv[8] = {w1a.x, w1a.y, w1a.z, w1a.w, w1b.x, w1b.y, w1b.z, w1b.w};
        float rv[8] = {r1a.x, r1a.y, r1a.z, r1a.w, r1b.x, r1b.y, r1b.z, r1b.w};
        float o[8];
        #pragma unroll
        for (int c = 0; c < 8; c++) o[c] = wv[c];
        #pragma unroll
        for (int d = 0; d < 8; d++) {
            float r = rv[d];
            #pragma unroll
            for (int c = 0; c < 8; c++)
                o[c] = fmaf(r, Vr[d * 64 + h1 * 8 + c], o[c]);
        }
        #pragma unroll
        for (int c = 0; c < 8; c++) o[c] *= inv;
        float4* op = (float4*)&out[(size_t)n1 * 64 + h1 * 8];
        op[0] = make_float4(o[0], o[1], o[2], o[3]);
        op[1] = make_float4(o[4], o[5], o[6], o[7]);
    }
}

// ============================================================
extern "C" void kernel_launch(void* const* d_in, const int* in_sizes, int n_in,
                              void* d_out, int out_size) {
    const float* x    = (const float*)d_in[0];
    const float* ea   = (const float*)d_in[1];
    const int*   ei   = (const int*)  d_in[2];
    const float* Wq   = (const float*)d_in[3];
    const float* bq   = (const float*)d_in[4];
    const float* Wk   = (const float*)d_in[5];
    const float* bk   = (const float*)d_in[6];
    const float* We   = (const float*)d_in[7];
    const float* be   = (const float*)d_in[8];
    const float* Wv   = (const float*)d_in[9];
    const float* bv   = (const float*)d_in[10];
    const float* Aw   = (const float*)d_in[11];
    const float* VeRow= (const float*)d_in[12];

    float* out = (float*)d_out;                  // h_out: [N, 64]
    float* wE  = out + (size_t)N_NODES * 64;     // wE:    [E, 64]

    cudaFuncSetAttribute(qkv_mma_kernel, cudaFuncAttributeMaxDynamicSharedMemorySize, QB_TOTAL);
    cudaFuncSetAttribute(edge_kernel,    cudaFuncAttributeMaxDynamicSharedMemorySize, SM_TOTAL);

    nop_kernel<<<1, 32>>>();   // keeps ncu capture slot on edge_kernel
    prep_kernel<<<80, 256>>>(Wq, Wk, Wv, We);
    qkv_mma_kernel<<<(N_NODES + 127) / 128, 256, QB_TOTAL>>>(x, bq, bk, bv);
    edge_kernel<<<N_EDGES / 128, 512, SM_TOTAL>>>(ea, ei, be, Aw, wE);
    finalize_kernel<<<(N_NODES * HEADS + 511) / 512, 256>>>(VeRow, out);
}

// round 17
// speedup vs baseline: 1.1505x; 1.1047x over previous
#include <cuda_runtime.h>
#include <cuda_bf16.h>
#include <math.h>
#include <cstdint>

#define N_NODES 50000
#define N_EDGES 800000
#define HEADS 8
#define HID 64
#define CLAMP_V 5.0f
#define LOG2E 1.44269504088896f

// ---------------- device scratch (zero-init at module load) ----------------
// g_Q/g_K/g_V/g_wV/g_row rows use the HEAD-INTERLEAVED layout:
//   row[p], p = (d>>2)*32 + h*4 + (d&3)   for logical (h, d)
// so the 8 lanes of one edge read/write ONE dense 128B line per 16B chunk.
__device__ float g_Q[N_NODES * HID];
__device__ float g_K[N_NODES * HID];
__device__ float g_V[N_NODES * HID];
__device__ float g_s[N_NODES * HEADS];
__device__ float g_wV[N_NODES * HID];
__device__ float g_row[N_NODES * HID];
// Pre-split weights, bf16 hi/lo, row-major [n][k]
__device__ __align__(16) unsigned short g_WhiT[192 * 64];   // [Wq|Wk|Wv]^T
__device__ __align__(16) unsigned short g_WloT[192 * 64];
__device__ __align__(16) unsigned short g_BhiT[128 * 64];   // We^T
__device__ __align__(16) unsigned short g_BloT[128 * 64];

// ---------------- helpers ----------------
__device__ __forceinline__ uint32_t smem_u32(const void* p) {
    uint32_t a;
    asm("{ .reg .u64 t; cvta.to.shared.u64 t, %1; cvt.u32.u64 %0, t; }" : "=r"(a) : "l"(p));
    return a;
}
__device__ __forceinline__ void red_add_v4(float* ptr, float a, float b, float c, float d) {
    asm volatile("red.global.add.v4.f32 [%0], {%1,%2,%3,%4};"
                 :: "l"(ptr), "f"(a), "f"(b), "f"(c), "f"(d) : "memory");
}
__device__ __forceinline__ float sqrt_approx(float x) {
    float r; asm("sqrt.approx.f32 %0, %1;" : "=f"(r) : "f"(x)); return r;
}
__device__ __forceinline__ float exp2_approx(float x) {
    float r; asm("ex2.approx.f32 %0, %1;" : "=f"(r) : "f"(x)); return r;
}
__device__ __forceinline__ void ldsm_x4(uint32_t& r0, uint32_t& r1, uint32_t& r2, uint32_t& r3,
                                        uint32_t addr) {
    asm volatile("ldmatrix.sync.aligned.m8n8.x4.shared.b16 {%0,%1,%2,%3}, [%4];"
                 : "=r"(r0), "=r"(r1), "=r"(r2), "=r"(r3) : "r"(addr));
}
// streaming (evict-first) global accesses — keep Q/K/V resident in L2
__device__ __forceinline__ float4 ldg_cs(const float4* p) {
    float4 v;
    asm("ld.global.cs.v4.f32 {%0,%1,%2,%3}, [%4];"
        : "=f"(v.x), "=f"(v.y), "=f"(v.z), "=f"(v.w) : "l"(p));
    return v;
}
__device__ __forceinline__ void stg_cs(float4* p, float4 v) {
    asm volatile("st.global.cs.v4.f32 [%0], {%1,%2,%3,%4};"
                 :: "l"(p), "f"(v.x), "f"(v.y), "f"(v.z), "f"(v.w) : "memory");
}
// hi/lo bf16 split of a float pair; packed regs in mem order [x, y]
__device__ __forceinline__ void split2(float x, float y, uint32_t& hi, uint32_t& lo) {
    uint32_t xb = __float_as_uint(x), yb = __float_as_uint(y);
    float xh = __uint_as_float((xb + 0x8000u) & 0xFFFF0000u);
    float yh = __uint_as_float((yb + 0x8000u) & 0xFFFF0000u);
    float xl = x - xh, yl = y - yh;
    asm("cvt.rn.bf16x2.f32 %0, %1, %2;" : "=r"(hi) : "f"(yh), "f"(xh));
    asm("cvt.rn.bf16x2.f32 %0, %1, %2;" : "=r"(lo) : "f"(yl), "f"(xl));
}
__device__ __forceinline__ void split1(float v, unsigned short& hs, unsigned short& ls) {
    uint32_t vb = __float_as_uint(v);
    float vh = __uint_as_float((vb + 0x8000u) & 0xFFFF0000u);
    float vl = v - vh;
    hs = (unsigned short)((vb + 0x8000u) >> 16);
    asm("cvt.rn.bf16.f32 %0, %1;" : "=h"(ls) : "f"(vl));
}
__device__ __forceinline__ void mma_bf16(float* c, const uint32_t* a, uint32_t b0, uint32_t b1) {
    asm volatile(
        "mma.sync.aligned.m16n8k16.row.col.f32.bf16.bf16.f32 "
        "{%0,%1,%2,%3}, {%4,%5,%6,%7}, {%8,%9}, {%0,%1,%2,%3};"
        : "+f"(c[0]), "+f"(c[1]), "+f"(c[2]), "+f"(c[3])
        : "r"(a[0]), "r"(a[1]), "r"(a[2]), "r"(a[3]), "r"(b0), "r"(b1));
}

// ============================================================
// Kernel -1: nop — keeps the ncu capture slot on edge_kernel
// ============================================================
__global__ void nop_kernel() {}

// ============================================================
// Kernel 0: prep — split weights into bf16 hi/lo global images
// ============================================================
__global__ void prep_kernel(const float* __restrict__ Wq, const float* __restrict__ Wk,
                            const float* __restrict__ Wv, const float* __restrict__ We) {
    int idx = blockIdx.x * 256 + threadIdx.x;
    if (idx < 192 * 64) {
        int n = idx >> 6, k = idx & 63;
        float v = (n < 64) ? Wq[k * 64 + n]
                : (n < 128) ? Wk[k * 64 + (n - 64)]
                            : Wv[k * 64 + (n - 128)];
        unsigned short hs, ls;
        split1(v, hs, ls);
        g_WhiT[idx] = hs;
        g_WloT[idx] = ls;
    } else if (idx < 192 * 64 + 128 * 64) {
        int j = idx - 192 * 64;
        int n = j >> 6, k = j & 63;
        unsigned short hs, ls;
        split1(We[k * 128 + n], hs, ls);
        g_BhiT[j] = hs;
        g_BloT[j] = ls;
    }
}

// ============================================================
// Kernel 1: QKV via mma.sync bf16 hi/lo.  128 rows/block, 256 thr.
// Epilogue stores into the head-interleaved layout.
// ============================================================
#define QB_BIAS 0                         // 192 floats
#define QB_AHI  1024                      // [128][72] bf16 = 18432
#define QB_ALO  (QB_AHI + 18432)
#define QB_BHI  (QB_ALO + 18432)          // [192][72] bf16 = 27648
#define QB_BLO  (QB_BHI + 27648)
#define QB_TOTAL (QB_BLO + 27648)         // 93184

__global__ __launch_bounds__(256, 2)
void qkv_mma_kernel(const float* __restrict__ x,
                    const float* __restrict__ bq, const float* __restrict__ bk,
                    const float* __restrict__ bv) {
    extern __shared__ char smc[];
    float* sbias = (float*)(smc + QB_BIAS);
    const int tid = threadIdx.x;
    const int row0 = blockIdx.x * 128;

    if (tid < 192)
        sbias[tid] = (tid < 64) ? bq[tid] : (tid < 128) ? bk[tid - 64] : bv[tid - 128];

    // A: x[row0..row0+127][0..63] -> bf16 hi/lo, rows padded to 72
    #pragma unroll
    for (int it = 0; it < 4; it++) {
        int idx = tid + it * 256;              // 0..1023 : r=idx>>3, k0=(idx&7)*8
        int r = idx >> 3, k0 = (idx & 7) * 8;
        float4 va = make_float4(0.f, 0.f, 0.f, 0.f), vb = va;
        if (row0 + r < N_NODES) {
            va = *(const float4*)&x[(size_t)(row0 + r) * 64 + k0];
            vb = *(const float4*)&x[(size_t)(row0 + r) * 64 + k0 + 4];
        }
        uint32_t h01, l01, h23, l23, h45, l45, h67, l67;
        split2(va.x, va.y, h01, l01);
        split2(va.z, va.w, h23, l23);
        split2(vb.x, vb.y, h45, l45);
        split2(vb.z, vb.w, h67, l67);
        uint32_t off = (uint32_t)r * 144 + k0 * 2;   // 16B aligned
        *(uint4*)(smc + QB_AHI + off) = make_uint4(h01, h23, h45, h67);
        *(uint4*)(smc + QB_ALO + off) = make_uint4(l01, l23, l45, l67);
    }
    // B: copy [192][64] -> [192][72], 16B chunks
    #pragma unroll
    for (int it = 0; it < 6; it++) {
        int idx = tid + it * 256;              // 0..1535 : r=idx>>3, c=(idx&7)*8
        int r = idx >> 3, c = (idx & 7) * 8;
        uint32_t off = (uint32_t)r * 144 + c * 2;
        *(uint4*)(smc + QB_BHI + off) = *(const uint4*)&g_WhiT[r * 64 + c];
        *(uint4*)(smc + QB_BLO + off) = *(const uint4*)&g_WloT[r * 64 + c];
    }
    __syncthreads();

    const int lane = tid & 31;
    const int w = tid >> 5;
    const int wm = w >> 1;                     // 0..3 : rows wm*32
    const int wn = w & 1;                      // 0..1 : cols wn*96 (12 n-tiles)
    const int g = lane >> 2, t2 = (lane & 3) * 2;

    const unsigned short* Ah = (const unsigned short*)(smc + QB_AHI);
    const unsigned short* Al = (const unsigned short*)(smc + QB_ALO);
    const unsigned short* Bh = (const unsigned short*)(smc + QB_BHI);
    const unsigned short* Bl = (const unsigned short*)(smc + QB_BLO);

    float acc[2][12][4];
    #pragma unroll
    for (int mt = 0; mt < 2; mt++)
        #pragma unroll
        for (int nt = 0; nt < 12; nt++)
            #pragma unroll
            for (int i = 0; i < 4; i++) acc[mt][nt][i] = 0.f;

    #pragma unroll
    for (int kk = 0; kk < 4; kk++) {
        const int k0 = kk * 16;
        uint32_t ah[2][4], al[2][4];
        #pragma unroll
        for (int mt = 0; mt < 2; mt++) {
            int r = wm * 32 + mt * 16 + g;
            ah[mt][0] = *(const uint32_t*)&Ah[(r    ) * 72 + k0 + t2];
            ah[mt][1] = *(const uint32_t*)&Ah[(r + 8) * 72 + k0 + t2];
            ah[mt][2] = *(const uint32_t*)&Ah[(r    ) * 72 + k0 + t2 + 8];
            ah[mt][3] = *(const uint32_t*)&Ah[(r + 8) * 72 + k0 + t2 + 8];
            al[mt][0] = *(const uint32_t*)&Al[(r    ) * 72 + k0 + t2];
            al[mt][1] = *(const uint32_t*)&Al[(r + 8) * 72 + k0 + t2];
            al[mt][2] = *(const uint32_t*)&Al[(r    ) * 72 + k0 + t2 + 8];
            al[mt][3] = *(const uint32_t*)&Al[(r + 8) * 72 + k0 + t2 + 8];
        }
        #pragma unroll
        for (int nt = 0; nt < 12; nt++) {
            int n = wn * 96 + nt * 8 + g;
            uint32_t bh0 = *(const uint32_t*)&Bh[n * 72 + k0 + t2];
            uint32_t bh1 = *(const uint32_t*)&Bh[n * 72 + k0 + t2 + 8];
            uint32_t bl0 = *(const uint32_t*)&Bl[n * 72 + k0 + t2];
            uint32_t bl1 = *(const uint32_t*)&Bl[n * 72 + k0 + t2 + 8];
            #pragma unroll
            for (int mt = 0; mt < 2; mt++) {
                mma_bf16(acc[mt][nt], ah[mt], bh0, bh1);
                mma_bf16(acc[mt][nt], ah[mt], bl0, bl1);
                mma_bf16(acc[mt][nt], al[mt], bh0, bh1);
            }
        }
    }

    // store fragments (head-interleaved layout; pairs stay contiguous)
    #pragma unroll
    for (int nt = 0; nt < 12; nt++) {
        int col = wn * 96 + nt * 8 + t2;
        float b0 = sbias[col], b1 = sbias[col + 1];
        float* arr = (col < 64) ? g_Q : (col < 128) ? g_K : g_V;
        int c = (col < 64) ? col : (col < 128) ? col - 64 : col - 128;
        int h = c >> 3, d = c & 7;
        int p = ((d >> 2) << 5) + h * 4 + (d & 3);   // interleaved position
        #pragma unroll
        for (int mt = 0; mt < 2; mt++) {
            int r = row0 + wm * 32 + mt * 16 + g;
            if (r < N_NODES)
                *(float2*)&arr[(size_t)r * 64 + p] = make_float2(acc[mt][nt][0] + b0, acc[mt][nt][1] + b1);
            if (r + 8 < N_NODES)
                *(float2*)&arr[(size_t)(r + 8) * 64 + p] = make_float2(acc[mt][nt][2] + b0, acc[mt][nt][3] + b1);
        }
    }
}

// ============================================================
// Kernel 2: fused edge kernel, 128 edges/block, 512 threads.
// Head-interleaved gathers/scatters: 1 dense line per 16B chunk.
// ============================================================
#define SM_BE    0                       // be[128] floats   (512B)
#define SM_AW    512                     // Aw[64] floats    (256B)
#define SM_EI    768                     // src[128], dst[128] ints (1024B)
#define SM_AHI   2048                    // [128][72] bf16 = 18432
#define SM_ALO   (SM_AHI + 18432)
#define SM_BHI   (SM_ALO + 18432)        // [128][72] bf16 = 18432
#define SM_BLO   (SM_BHI + 18432)
#define SM_ES    2048                    // alias: [128 edges][164] floats
#define ES_STRIDE 164
#define SM_TOTAL (2048 + 128 * ES_STRIDE * 4)   // 86016
#define CLAMP2   (CLAMP_V * LOG2E)       // 7.2134752

__global__ __launch_bounds__(512, 2)
void edge_kernel(const float* __restrict__ ea,
                 const int*   __restrict__ ei,
                 const float* __restrict__ be,
                 const float* __restrict__ Aw,
                 float* __restrict__ wE) {
    extern __shared__ char smc[];
    float* sbe = (float*)(smc + SM_BE);
    float* sAw = (float*)(smc + SM_AW);
    int*   sei = (int*)  (smc + SM_EI);     // [0..127]=src, [128..255]=dst
    const int tid = threadIdx.x;
    const int e0 = blockIdx.x * 128;

    if (tid < 128) sbe[tid] = be[tid];
    else if (tid < 192) sAw[tid - 128] = Aw[tid - 128] * LOG2E;   // exp2 pre-scale
    else if (tid < 320) sei[tid - 192] = ei[e0 + tid - 192];                 // src
    else if (tid < 448) sei[tid - 320 + 128] = ei[N_EDGES + e0 + tid - 320]; // dst

    // A: ea[e0..e0+127][0..63] -> bf16 hi/lo, rows padded to 72 (streaming reads, 16B stores)
    #pragma unroll
    for (int it = 0; it < 2; it++) {
        int idx = tid + it * 512;          // 0..1023 : r=idx>>3, k0=(idx&7)*8
        int r = idx >> 3, k0 = (idx & 7) * 8;
        float4 va = ldg_cs((const float4*)&ea[(size_t)(e0 + r) * 64 + k0]);
        float4 vb = ldg_cs((const float4*)&ea[(size_t)(e0 + r) * 64 + k0 + 4]);
        uint32_t h01, l01, h23, l23, h45, l45, h67, l67;
        split2(va.x, va.y, h01, l01);
        split2(va.z, va.w, h23, l23);
        split2(vb.x, vb.y, h45, l45);
        split2(vb.z, vb.w, h67, l67);
        uint32_t off = (uint32_t)r * 144 + k0 * 2;   // 16B aligned
        *(uint4*)(smc + SM_AHI + off) = make_uint4(h01, h23, h45, h67);
        *(uint4*)(smc + SM_ALO + off) = make_uint4(l01, l23, l45, l67);
    }
    // B: copy [128][64] -> [128][72], 16B chunks
    #pragma unroll
    for (int it = 0; it < 2; it++) {
        int idx = tid + it * 512;          // 0..1023 : r=idx>>3, c=(idx&7)*8
        int r = idx >> 3, c = (idx & 7) * 8;
        uint32_t off = (uint32_t)r * 144 + c * 2;
        *(uint4*)(smc + SM_BHI + off) = *(const uint4*)&g_BhiT[r * 64 + c];
        *(uint4*)(smc + SM_BLO + off) = *(const uint4*)&g_BloT[r * 64 + c];
    }
    __syncthreads();

    // -------- GEMM: D[128 x 128] = A(128x64) @ B^T(128x64)^T, 3-term --------
    const int lane = tid & 31;
    const int w = tid >> 5;                // 0..15
    const int wm = w >> 2;                 // 0..3 : rows wm*32
    const int wn = w & 3;                  // 0..3 : cols wn*32
    const int g = lane >> 2, t2 = (lane & 3) * 2;
    const uint32_t sb = smem_u32(smc);

    // ldmatrix lane-offset maps (bytes):
    const uint32_t aoff = (uint32_t)((lane & 15) * 72 + ((lane >> 4) << 3)) * 2;
    const uint32_t boff = (uint32_t)(((lane >> 4) * 8 + (lane & 7)) * 72 + ((lane >> 3) & 1) * 8) * 2;

    const uint32_t aHi = sb + SM_AHI + (uint32_t)(wm * 32) * 144 + aoff;
    const uint32_t aLo = sb + SM_ALO + (uint32_t)(wm * 32) * 144 + aoff;
    const uint32_t bHi = sb + SM_BHI + (uint32_t)(wn * 32) * 144 + boff;
    const uint32_t bLo = sb + SM_BLO + (uint32_t)(wn * 32) * 144 + boff;

    float acc[2][4][4];
    #pragma unroll
    for (int mt = 0; mt < 2; mt++)
        #pragma unroll
        for (int nt = 0; nt < 4; nt++)
            #pragma unroll
            for (int i = 0; i < 4; i++) acc[mt][nt][i] = 0.f;

    #pragma unroll
    for (int kk = 0; kk < 4; kk++) {
        const uint32_t kb = (uint32_t)kk * 32;   // 16 bf16 = 32 bytes per k-step
        uint32_t ah[2][4], al[2][4];
        ldsm_x4(ah[0][0], ah[0][1], ah[0][2], ah[0][3], aHi + kb);
        ldsm_x4(ah[1][0], ah[1][1], ah[1][2], ah[1][3], aHi + 16 * 144 + kb);
        ldsm_x4(al[0][0], al[0][1], al[0][2], al[0][3], aLo + kb);
        ldsm_x4(al[1][0], al[1][1], al[1][2], al[1][3], aLo + 16 * 144 + kb);
        uint32_t bh[8], bl[8];   // [nt*2 + khalf]
        ldsm_x4(bh[0], bh[1], bh[2], bh[3], bHi + kb);              // nt0, nt1
        ldsm_x4(bh[4], bh[5], bh[6], bh[7], bHi + 16 * 144 + kb);   // nt2, nt3
        ldsm_x4(bl[0], bl[1], bl[2], bl[3], bLo + kb);
        ldsm_x4(bl[4], bl[5], bl[6], bl[7], bLo + 16 * 144 + kb);
        #pragma unroll
        for (int nt = 0; nt < 4; nt++) {
            #pragma unroll
            for (int mt = 0; mt < 2; mt++) {
                mma_bf16(acc[mt][nt], ah[mt], bh[nt * 2], bh[nt * 2 + 1]);
                mma_bf16(acc[mt][nt], ah[mt], bl[nt * 2], bl[nt * 2 + 1]);
                mma_bf16(acc[mt][nt], al[mt], bh[nt * 2], bh[nt * 2 + 1]);
            }
        }
    }
    __syncthreads();   // all A/B reads done before Es aliases the region

    // stage D + bias into Es: layout [edge][164], heads at h*20 (STS.64)
    float* Es = (float*)(smc + SM_ES);
    #pragma unroll
    for (int mt = 0; mt < 2; mt++) {
        #pragma unroll
        for (int nt = 0; nt < 4; nt++) {
            int row = wm * 32 + mt * 16 + g;
            int col = wn * 32 + nt * 8 + t2;
            int h = col >> 4, d = col & 15;
            float b0 = sbe[col], b1 = sbe[col + 1];
            *(float2*)&Es[row * ES_STRIDE + h * 20 + d] =
                make_float2(acc[mt][nt][0] + b0, acc[mt][nt][1] + b1);
            *(float2*)&Es[(row + 8) * ES_STRIDE + h * 20 + d] =
                make_float2(acc[mt][nt][2] + b0, acc[mt][nt][3] + b1);
        }
    }
    __syncthreads();

    // -------- Phase B: 1024 items = 128 edges x 8 heads, 2 per thread --------
    #pragma unroll
    for (int it = 0; it < 2; it++) {
        int item = tid + it * 512;
        int le = item >> 3;
        int h  = item & 7;
        int e  = e0 + le;
        int src = sei[le];
        int dst = sei[128 + le];

        // head-interleaved: chunk0 (dims 0-3) at h*4, chunk1 (dims 4-7) at 32+h*4
        const float* Kb = &g_K[(size_t)src * 64];
        const float* Qb = &g_Q[(size_t)dst * 64];
        const float* Vb = &g_V[(size_t)src * 64];
        float4 k0 = *(const float4*)&Kb[h * 4];
        float4 k1 = *(const float4*)&Kb[32 + h * 4];
        float4 q0 = *(const float4*)&Qb[h * 4];
        float4 q1 = *(const float4*)&Qb[32 + h * 4];
        float4 v0 = *(const float4*)&Vb[h * 4];
        float4 v1 = *(const float4*)&Vb[32 + h * 4];

        float t[8];
        t[0] = k0.x + q0.x; t[1] = k0.y + q0.y; t[2] = k0.z + q0.z; t[3] = k0.w + q0.w;
        t[4] = k1.x + q1.x; t[5] = k1.y + q1.y; t[6] = k1.z + q1.z; t[7] = k1.w + q1.w;

        const float* ep = &Es[le * ES_STRIDE + h * 20];
        float4 ew0 = *(const float4*)&ep[0];
        float4 ew1 = *(const float4*)&ep[4];
        float4 eb0 = *(const float4*)&ep[8];
        float4 eb1 = *(const float4*)&ep[12];
        float ew[8] = {ew0.x, ew0.y, ew0.z, ew0.w, ew1.x, ew1.y, ew1.z, ew1.w};
        float eb[8] = {eb0.x, eb0.y, eb0.z, eb0.w, eb1.x, eb1.y, eb1.z, eb1.w};

        float et[8];
        #pragma unroll
        for (int d = 0; d < 8; d++) {
            float u = t[d] * ew[d];
            float sc = copysignf(sqrt_approx(fabsf(u)), u) + eb[d];
            et[d] = fmaxf(sc, 0.f);
        }

        float4* wp = (float4*)&wE[(size_t)e * 64 + h * 8];
        stg_cs(wp,     make_float4(et[0], et[1], et[2], et[3]));
        stg_cs(wp + 1, make_float4(et[4], et[5], et[6], et[7]));

        float a = 0.f;
        #pragma unroll
        for (int d = 0; d < 8; d++) a = fmaf(et[d], sAw[d * 8 + h], a);
        a = fminf(fmaxf(a, -CLAMP2), CLAMP2);
        float p = exp2_approx(a);

        atomicAdd(&g_s[(size_t)dst * 8 + h], p);
        float* wvb = &g_wV[(size_t)dst * 64];
        red_add_v4(&wvb[h * 4],      p * v0.x, p * v0.y, p * v0.z, p * v0.w);
        red_add_v4(&wvb[32 + h * 4], p * v1.x, p * v1.y, p * v1.z, p * v1.w);
        float* rwb = &g_row[(size_t)dst * 64];
        red_add_v4(&rwb[h * 4],      p * et[0], p * et[1], p * et[2], p * et[3]);
        red_add_v4(&rwb[32 + h * 4], p * et[4], p * et[5], p * et[6], p * et[7]);
    }
}

// ============================================================
// Kernel 3: finalize (2 items/thread, loads batched for MLP)
//           reads head-interleaved accumulators; self-zeros scratch
// ============================================================
__global__ __launch_bounds__(256, 6)
void finalize_kernel(const float* __restrict__ VeRow,
                     float* __restrict__ out) {
    __shared__ float Vr[512];
    const int tid = threadIdx.x;
    for (int i = tid; i < 512; i += 256) Vr[i] = VeRow[i];
    __syncthreads();

    const int i0 = blockIdx.x * 512 + tid;
    const int i1 = i0 + 256;
    if (i0 >= N_NODES * HEADS) return;
    const bool has1 = (i1 < N_NODES * HEADS);

    const int n0 = i0 >> 3, h0 = i0 & 7;
    const int n1 = i1 >> 3, h1 = i1 & 7;

    // ---- issue ALL loads up front (10 independent requests) ----
    float s0 = g_s[i0];
    float s1 = has1 ? g_s[i1] : 1.f;
    float4* wp0a = (float4*)&g_wV[(size_t)n0 * 64 + h0 * 4];
    float4* wp0b = (float4*)&g_wV[(size_t)n0 * 64 + 32 + h0 * 4];
    float4* rp0a = (float4*)&g_row[(size_t)n0 * 64 + h0 * 4];
    float4* rp0b = (float4*)&g_row[(size_t)n0 * 64 + 32 + h0 * 4];
    float4* wp1a = (float4*)&g_wV[(size_t)n1 * 64 + h1 * 4];
    float4* wp1b = (float4*)&g_wV[(size_t)n1 * 64 + 32 + h1 * 4];
    float4* rp1a = (float4*)&g_row[(size_t)n1 * 64 + h1 * 4];
    float4* rp1b = (float4*)&g_row[(size_t)n1 * 64 + 32 + h1 * 4];
    float4 w0a = wp0a[0], w0b = wp0b[0];
    float4 r0a = rp0a[0], r0b = rp0b[0];
    float4 w1a, w1b, r1a, r1b;
    if (has1) { w1a = wp1a[0]; w1b = wp1b[0]; r1a = rp1a[0]; r1b = rp1b[0]; }

    // ---- zero-stores for next replay ----
    float4 z = make_float4(0.f, 0.f, 0.f, 0.f);
    g_s[i0] = 0.f;
    wp0a[0] = z; wp0b[0] = z; rp0a[0] = z; rp0b[0] = z;
    if (has1) { g_s[i1] = 0.f; wp1a[0] = z; wp1b[0] = z; rp1a[0] = z; rp1b[0] = z; }

    // ---- compute item 0 ----
    {
        float inv = 1.f / (s0 + 1e-16f);
        float wv[8] = {w0a.x, w0a.y, w0a.z, w0a.w, w0b.x, w0b.y, w0b.z, w0b.w};
        float rv[8] = {r0a.x, r0a.y, r0a.z, r0a.w, r0b.x, r0b.y, r0b.z, r0b.w};
        float o[8];
        #pragma unroll
        for (int c = 0; c < 8; c++) o[c] = wv[c];
        #pragma unroll
        for (int d = 0; d < 8; d++) {
            float r = rv[d];
            #pragma unroll
            for (int c = 0; c < 8; c++)
                o[c] = fmaf(r, Vr[d * 64 + h0 * 8 + c], o[c]);
        }
        #pragma unroll
        for (int c = 0; c < 8; c++) o[c] *= inv;
        float4* op = (float4*)&out[(size_t)n0 * 64 + h0 * 8];
        op[0] = make_float4(o[0], o[1], o[2], o[3]);
        op[1] = make_float4(o[4], o[5], o[6], o[7]);
    }
    // ---- compute item 1 ----
    if (has1) {
        float inv = 1.f / (s1 + 1e-16f);
        float wv[8] = {w1a.x, w1a.y, w1a.z, w1a.w, w1b.x, w1b.y, w1b.z, w1b.w};
        float rv[8] = {r1a.x, r1a.y, r1a.z, r1a.w, r1b.x, r1b.y, r1b.z, r1b.w};
        float o[8];
        #pragma unroll
        for (int c = 0; c < 8; c++) o[c] = wv[c];
        #pragma unroll
        for (int d = 0; d < 8; d++) {
            float r = rv[d];
            #pragma unroll
            for (int c = 0; c < 8; c++)
                o[c] = fmaf(r, Vr[d * 64 + h1 * 8 + c], o[c]);
        }
        #pragma unroll
        for (int c = 0; c < 8; c++) o[c] *= inv;
        float4* op = (float4*)&out[(size_t)n1 * 64 + h1 * 8];
        op[0] = make_float4(o[0], o[1], o[2], o[3]);
        op[1] = make_float4(o[4], o[5], o[6], o[7]);
    }
}

// ============================================================
extern "C" void kernel_launch(void* const* d_in, const int* in_sizes, int n_in,
                              void* d_out, int out_size) {
    const float* x    = (const float*)d_in[0];
    const float* ea   = (const float*)d_in[1];
    const int*   ei   = (const int*)  d_in[2];
    const float* Wq   = (const float*)d_in[3];
    const float* bq   = (const float*)d_in[4];
    const float* Wk   = (const float*)d_in[5];
    const float* bk   = (const float*)d_in[6];
    const float* We   = (const float*)d_in[7];
    const float* be   = (const float*)d_in[8];
    const float* Wv   = (const float*)d_in[9];
    const float* bv   = (const float*)d_in[10];
    const float* Aw   = (const float*)d_in[11];
    const float* VeRow= (const float*)d_in[12];

    float* out = (float*)d_out;                  // h_out: [N, 64]
    float* wE  = out + (size_t)N_NODES * 64;     // wE:    [E, 64]

    cudaFuncSetAttribute(qkv_mma_kernel, cudaFuncAttributeMaxDynamicSharedMemorySize, QB_TOTAL);
    cudaFuncSetAttribute(edge_kernel,    cudaFuncAttributeMaxDynamicSharedMemorySize, SM_TOTAL);

    nop_kernel<<<1, 32>>>();   // keeps ncu capture slot on edge_kernel
    prep_kernel<<<80, 256>>>(Wq, Wk, Wv, We);
    qkv_mma_kernel<<<(N_NODES + 127) / 128, 256, QB_TOTAL>>>(x, bq, bk, bv);
    edge_kernel<<<N_EDGES / 128, 512, SM_TOTAL>>>(ea, ei, be, Aw, wE);
    finalize_kernel<<<(N_NODES * HEADS + 511) / 512, 256>>>(VeRow, out);
}